// round 1
// baseline (speedup 1.0000x reference)
#include <cuda_runtime.h>
#include <cstdint>

#define K_CODES 4096
#define D_DIM   64
#define N_ROWS  65536
#define NTOT    (N_ROWS * D_DIM)   // 4194304
#define M_TILE  64
#define KT      128
#define THREADS 256
#define NBLOCKS (N_ROWS / M_TILE)  // 1024

// ---- scratch (no allocations allowed) ----
__device__ float g_eT[K_CODES * D_DIM];   // transposed codebook [k][d]
__device__ float g_enorm[K_CODES];        // ||e_k||^2
__device__ float g_p1[NBLOCKS];           // per-block sum(q - x)
__device__ float g_p2[NBLOCKS];           // per-block sum((q - x)^2)

// ---- packed f32x2 helpers (Blackwell FFMA2 path) ----
static __device__ __forceinline__ unsigned long long pack2(float lo, float hi) {
    unsigned long long r;
    asm("mov.b64 %0, {%1, %2};" : "=l"(r) : "f"(lo), "f"(hi));
    return r;
}
static __device__ __forceinline__ void unpack2(unsigned long long v, float &lo, float &hi) {
    asm("mov.b64 {%0, %1}, %2;" : "=f"(lo), "=f"(hi) : "l"(v));
}
static __device__ __forceinline__ unsigned long long fma2(
        unsigned long long a, unsigned long long b, unsigned long long c) {
    unsigned long long d;
    asm("fma.rn.f32x2 %0, %1, %2, %3;" : "=l"(d) : "l"(a), "l"(b), "l"(c));
    return d;
}

// ---- prep: transpose codebook + column norms ----
__global__ void vq_prep(const float* __restrict__ emb) {
    int k = blockIdx.x * blockDim.x + threadIdx.x;
    if (k >= K_CODES) return;
    float acc = 0.0f;
#pragma unroll
    for (int d = 0; d < D_DIM; ++d) {
        float v = emb[d * K_CODES + k];
        g_eT[k * D_DIM + d] = v;
        acc += v * v;
    }
    g_enorm[k] = acc;
}

// ---- main: distances + argmin + gather + loss partials ----
__global__ __launch_bounds__(THREADS) void vq_main(
        const float* __restrict__ x,
        const float* __restrict__ emb,
        float* __restrict__ out) {
    __shared__ float fsm[D_DIM][M_TILE];   // x tile, transposed: [d][row]  16KB
    __shared__ float esm[D_DIM][KT];       // codebook tile:      [d][k]    32KB

    const int tid = threadIdx.x;
    const int kg  = tid & 31;   // lane: k-group (4 codes each)
    const int rg  = tid >> 5;   // warp id: row-group (8 rows each)
    const int rowBase = blockIdx.x * M_TILE;

    // load x tile transposed (coalesced gmem read; smem scatter is one-time)
    for (int idx = tid; idx < M_TILE * D_DIM; idx += THREADS) {
        int r = idx >> 6;
        int d = idx & 63;
        fsm[d][r] = x[(rowBase + r) * D_DIM + d];
    }

    float minv[8];
    int   mini[8];
#pragma unroll
    for (int j = 0; j < 8; ++j) { minv[j] = __int_as_float(0x7f800000); mini[j] = 0; }

    const unsigned long long neg2 = pack2(-2.0f, -2.0f);

    for (int t = 0; t < K_CODES / KT; ++t) {
        __syncthreads();   // also covers fsm stores on first iteration
        {
            const float* ebase = emb + t * KT;
            for (int idx = tid; idx < D_DIM * KT; idx += THREADS) {
                int d  = idx >> 7;
                int kk = idx & (KT - 1);
                esm[d][kk] = ebase[d * K_CODES + kk];
            }
        }
        __syncthreads();

        // acc[rowpair][k] : dot(f_row, e_k) packed over row pairs
        unsigned long long acc[4][4];
#pragma unroll
        for (int a = 0; a < 4; ++a)
#pragma unroll
            for (int b = 0; b < 4; ++b) acc[a][b] = 0ull;

#pragma unroll 8
        for (int d = 0; d < D_DIM; ++d) {
            // 4 row-pairs of f (broadcast within warp), as f32x2 directly
            unsigned long long fp0 = *(const unsigned long long*)&fsm[d][rg * 8 + 0];
            unsigned long long fp1 = *(const unsigned long long*)&fsm[d][rg * 8 + 2];
            unsigned long long fp2 = *(const unsigned long long*)&fsm[d][rg * 8 + 4];
            unsigned long long fp3 = *(const unsigned long long*)&fsm[d][rg * 8 + 6];
            // 4 e values, broadcast-packed
            float4 ev = *(const float4*)&esm[d][kg * 4];
            unsigned long long e0 = pack2(ev.x, ev.x);
            unsigned long long e1 = pack2(ev.y, ev.y);
            unsigned long long e2 = pack2(ev.z, ev.z);
            unsigned long long e3 = pack2(ev.w, ev.w);

            acc[0][0] = fma2(fp0, e0, acc[0][0]);
            acc[1][0] = fma2(fp1, e0, acc[1][0]);
            acc[2][0] = fma2(fp2, e0, acc[2][0]);
            acc[3][0] = fma2(fp3, e0, acc[3][0]);
            acc[0][1] = fma2(fp0, e1, acc[0][1]);
            acc[1][1] = fma2(fp1, e1, acc[1][1]);
            acc[2][1] = fma2(fp2, e1, acc[2][1]);
            acc[3][1] = fma2(fp3, e1, acc[3][1]);
            acc[0][2] = fma2(fp0, e2, acc[0][2]);
            acc[1][2] = fma2(fp1, e2, acc[1][2]);
            acc[2][2] = fma2(fp2, e2, acc[2][2]);
            acc[3][2] = fma2(fp3, e2, acc[3][2]);
            acc[0][3] = fma2(fp0, e3, acc[0][3]);
            acc[1][3] = fma2(fp1, e3, acc[1][3]);
            acc[2][3] = fma2(fp2, e3, acc[2][3]);
            acc[3][3] = fma2(fp3, e3, acc[3][3]);
        }

        // scores: s = ||e||^2 - 2*dot  (||f||^2 is constant per row -> dropped)
#pragma unroll
        for (int kk = 0; kk < 4; ++kk) {
            int k = t * KT + kg * 4 + kk;
            float en = __ldg(&g_enorm[k]);
            unsigned long long enp = pack2(en, en);
#pragma unroll
            for (int rp = 0; rp < 4; ++rp) {
                unsigned long long s2 = fma2(acc[rp][kk], neg2, enp);
                float s0, s1;
                unpack2(s2, s0, s1);
                int r0 = 2 * rp, r1 = 2 * rp + 1;
                if (s0 < minv[r0]) { minv[r0] = s0; mini[r0] = k; }
                if (s1 < minv[r1]) { minv[r1] = s1; mini[r1] = k; }
            }
        }
    }

    // warp-level argmin reduction (lanes of a warp share the same 8 rows)
#pragma unroll
    for (int j = 0; j < 8; ++j) {
        float v = minv[j];
        int   idx = mini[j];
        for (int off = 16; off > 0; off >>= 1) {
            float ov = __shfl_xor_sync(0xffffffffu, v, off);
            int   oi = __shfl_xor_sync(0xffffffffu, idx, off);
            if (ov < v || (ov == v && oi < idx)) { v = ov; idx = oi; }
        }
        minv[j] = v;
        mini[j] = idx;
    }

    // gather codewords, write estimator (== quantized), accumulate loss partials
    float s1 = 0.0f, s2 = 0.0f;
#pragma unroll
    for (int j = 0; j < 8; ++j) {
        int n = rowBase + rg * 8 + j;
        const float* eT = &g_eT[mini[j] * D_DIM];
        int d0 = kg, d1 = kg + 32;
        float q0 = __ldg(&eT[d0]);
        float q1 = __ldg(&eT[d1]);
        float x0 = x[n * D_DIM + d0];
        float x1 = x[n * D_DIM + d1];
        out[n * D_DIM + d0] = q0;
        out[n * D_DIM + d1] = q1;
        float dd0 = q0 - x0, dd1 = q1 - x1;
        s1 += dd0 + dd1;
        s2 += dd0 * dd0 + dd1 * dd1;
    }

    // block reduction of loss partials (deterministic tree), reuse esm
    __syncthreads();
    float* red = &esm[0][0];
    red[tid]           = s1;
    red[THREADS + tid] = s2;
    __syncthreads();
    for (int stride = THREADS / 2; stride > 0; stride >>= 1) {
        if (tid < stride) {
            red[tid]           += red[tid + stride];
            red[THREADS + tid] += red[THREADS + tid + stride];
        }
        __syncthreads();
    }
    if (tid == 0) {
        g_p1[blockIdx.x] = red[0];
        g_p2[blockIdx.x] = red[THREADS];
    }
}

// ---- finalize: deterministic reduction of per-block partials -> loss ----
__global__ void vq_finalize(float* __restrict__ out, int out_size) {
    __shared__ float r1[NBLOCKS];
    __shared__ float r2[NBLOCKS];
    int t = threadIdx.x;
    r1[t] = g_p1[t];
    r2[t] = g_p2[t];
    __syncthreads();
    for (int stride = NBLOCKS / 2; stride > 0; stride >>= 1) {
        if (t < stride) { r1[t] += r1[t + stride]; r2[t] += r2[t + stride]; }
        __syncthreads();
    }
    if (t == 0 && out_size > NTOT) {
        float inv = 1.0f / (float)NTOT;
        float m   = r1[0] * inv;
        float loss = 0.25f * m * m + r2[0] * inv;
        out[NTOT] = loss;
    }
}

extern "C" void kernel_launch(void* const* d_in, const int* in_sizes, int n_in,
                              void* d_out, int out_size) {
    const float* x   = (const float*)d_in[0];
    const float* emb = (const float*)d_in[1];
    // defensive: identify by size (x has 4194304 elems, embedding 262144)
    if (n_in >= 2 && in_sizes[0] == K_CODES * D_DIM && in_sizes[1] == NTOT) {
        emb = (const float*)d_in[0];
        x   = (const float*)d_in[1];
    }
    float* out = (float*)d_out;

    vq_prep<<<(K_CODES + 255) / 256, 256>>>(emb);
    vq_main<<<NBLOCKS, THREADS>>>(x, emb, out);
    vq_finalize<<<1, NBLOCKS>>>(out, out_size);
}

// round 3
// speedup vs baseline: 2.1482x; 2.1482x over previous
#include <cuda_runtime.h>
#include <cuda_fp16.h>
#include <cstdint>

#define K_CODES 4096
#define D_DIM   64
#define N_ROWS  65536
#define NTOT    (N_ROWS * D_DIM)
#define NPC     32              // codes per chunk
#define NCHUNK  (K_CODES / NPC) // 128
#define ROWB    272             // bytes per padded row (128 halves + 8 pad)
#define BCH     (NPC * ROWB)    // 8704 bytes per B chunk
#define GEMM_CTAS (N_ROWS / 128)  // 512
#define MARGIN  1.5e-3f
#define GATHER_BLOCKS 1024

#define OFF_EN   34816u          // A-stage (128*272=34816) reused as 3x B buffers
#define SMEM_DYN (34816u + 16384u)

// ---------------- global scratch ----------------
__device__ float g_eT[K_CODES * D_DIM];          // codebook rows [k][d] fp32
__device__ float g_enorm[K_CODES];               // ||e_k||^2 fp32
__device__ int   g_idx[N_ROWS];
__device__ int   g_nflag;
__device__ int   g_flagrows[N_ROWS];
__device__ float g_p1[GATHER_BLOCKS];
__device__ float g_p2[GATHER_BLOCKS];
__device__ __align__(16) unsigned char g_Bsw[K_CODES * ROWB];   // fp16 [eh|eh|pad]

// ---------------- asm helpers ----------------
static __device__ __forceinline__ uint32_t smem_u32(const void* p) {
    uint32_t a;
    asm("{ .reg .u64 t; cvta.to.shared.u64 t, %1; cvt.u32.u64 %0, t; }" : "=r"(a) : "l"(p));
    return a;
}
static __device__ __forceinline__ void cpasync16(uint32_t s, const void* g) {
    asm volatile("cp.async.cg.shared.global [%0], [%1], 16;" :: "r"(s), "l"(g) : "memory");
}
#define CP_COMMIT() asm volatile("cp.async.commit_group;" ::: "memory")
#define CP_WAIT2()  asm volatile("cp.async.wait_group 2;"  ::: "memory")

#define LDMX4(r, addr) \
    asm volatile("ldmatrix.sync.aligned.m8n8.x4.shared.b16 {%0,%1,%2,%3}, [%4];" \
        : "=r"((r)[0]), "=r"((r)[1]), "=r"((r)[2]), "=r"((r)[3]) : "r"(addr))

#define MMA16816(d, a, b0, b1) \
    asm volatile("mma.sync.aligned.m16n8k16.row.col.f32.f16.f16.f32 " \
        "{%0,%1,%2,%3}, {%4,%5,%6,%7}, {%8,%9}, {%0,%1,%2,%3};" \
        : "+f"((d)[0]), "+f"((d)[1]), "+f"((d)[2]), "+f"((d)[3]) \
        : "r"((a)[0]), "r"((a)[1]), "r"((a)[2]), "r"((a)[3]), "r"(b0), "r"(b1))

static __device__ __forceinline__ uint32_t h2u(__half2 h) {
    union { __half2 h; uint32_t u; } c; c.h = h; return c.u;
}

// ---------------- prep: split codebook to fp16, build smem image ----------------
__global__ void prep_e(const float* __restrict__ emb) {
    int n = blockIdx.x * blockDim.x + threadIdx.x;
    if (n == 0) g_nflag = 0;
    if (n >= K_CODES) return;
    float acc = 0.0f;
    union { uint4 q[8]; __half h[64]; } eh;
#pragma unroll
    for (int d = 0; d < D_DIM; ++d) {
        float v = __ldg(&emb[d * K_CODES + n]);
        g_eT[n * D_DIM + d] = v;
        acc += v * v;
        eh.h[d] = __float2half_rn(v);
    }
    g_enorm[n] = acc;
    uint4* row = (uint4*)(g_Bsw + n * ROWB);
#pragma unroll
    for (int i = 0; i < 8; ++i) { row[i] = eh.q[i]; row[8 + i] = eh.q[i]; }
}

// ---------------- main GEMM: per-row (min1, min2, idx) ----------------
__global__ __launch_bounds__(256, 2) void vq_gemm(const float* __restrict__ x) {
    extern __shared__ __align__(16) unsigned char sm[];
    const uint32_t sb = smem_u32(sm);
    const int tid  = threadIdx.x;
    const int lane = tid & 31;
    const int w    = tid >> 5;
    const int rowBase = blockIdx.x * 128;

    // en -> smem (cp.async group 0)
    for (int i = tid; i < 1024; i += 256)
        cpasync16(sb + OFF_EN + (uint32_t)i * 16, (const char*)g_enorm + i * 16);
    CP_COMMIT();

    // A: load x, fp16 hi/lo split into smem rows [xh(128B) | xl(128B) | pad]
#pragma unroll
    for (int j = 0; j < 8; ++j) {
        int idx = tid + j * 256;           // 2048 float4 total
        int r = idx >> 4, dg = idx & 15;
        float4 v = __ldg((const float4*)(x + (size_t)(rowBase + r) * 64 + dg * 4));
        __half2 h01 = __floats2half2_rn(v.x, v.y);
        __half2 h23 = __floats2half2_rn(v.z, v.w);
        float2 f01 = __half22float2(h01);
        float2 f23 = __half22float2(h23);
        __half2 l01 = __floats2half2_rn(v.x - f01.x, v.y - f01.y);
        __half2 l23 = __floats2half2_rn(v.z - f23.x, v.w - f23.y);
        *(uint2*)(sm + r * ROWB + dg * 8)       = make_uint2(h2u(h01), h2u(h23));
        *(uint2*)(sm + r * ROWB + 128 + dg * 8) = make_uint2(h2u(l01), h2u(l23));
    }
    __syncthreads();

    // A fragments -> registers (held for entire mainloop)
    uint32_t afr[8][4];
    {
        uint32_t aAddr = sb + (uint32_t)(w * 16 + (lane & 15)) * ROWB
                       + (uint32_t)((lane >> 4) * 8) * 2;
#pragma unroll
        for (int s = 0; s < 8; ++s) LDMX4(afr[s], aAddr + (uint32_t)s * 32);
    }
    __syncthreads();   // A smem region free -> B buffers

    // B chunk pipeline (3-stage)
    auto issueB = [&](int c) {
        const char* gB = (const char*)g_Bsw + (size_t)c * BCH;
        uint32_t dst = sb + (uint32_t)(c % 3) * BCH;
        for (int i = tid; i < 544; i += 256)
            cpasync16(dst + (uint32_t)i * 16, gB + i * 16);
    };
    issueB(0); CP_COMMIT();
    issueB(1); CP_COMMIT();

    float m1a = 3.0e38f, m2a = 3.0e38f, m1b = 3.0e38f, m2b = 3.0e38f;
    int idxa = 0, idxb = 0;

    const uint32_t n_in  = (uint32_t)((lane & 7) + ((lane >> 4) << 3));
    const uint32_t khalf = (uint32_t)((lane >> 3) & 1);
    const uint32_t bLane = n_in * ROWB + khalf * 16;
    const float* en = (const float*)(sm + OFF_EN);

    for (int t = 0; t < NCHUNK; ++t) {
        __syncthreads();                      // buf[(t+2)%3] free (t-1 compute done)
        if (t + 2 < NCHUNK) issueB(t + 2);
        CP_COMMIT();
        CP_WAIT2();                           // chunk t landed
        __syncthreads();

        const uint32_t bbase = sb + (uint32_t)(t % 3) * BCH + bLane;
        float acc[4][4];
#pragma unroll
        for (int j = 0; j < 4; ++j)
#pragma unroll
            for (int c = 0; c < 4; ++c) acc[j][c] = 0.0f;

#pragma unroll
        for (int s = 0; s < 8; ++s) {
            uint32_t bf0[4], bf1[4];
            LDMX4(bf0, bbase + (uint32_t)s * 32);                 // n-tiles 0,1
            LDMX4(bf1, bbase + (uint32_t)s * 32 + 16u * ROWB);    // n-tiles 2,3
            MMA16816(acc[0], afr[s], bf0[0], bf0[1]);
            MMA16816(acc[1], afr[s], bf0[2], bf0[3]);
            MMA16816(acc[2], afr[s], bf1[0], bf1[1]);
            MMA16816(acc[3], afr[s], bf1[2], bf1[3]);
        }

        // epilogue: scores s = en - 2*dot; track (min1, min2, idx) per row
        const int nb = t * NPC + 2 * (lane & 3);
#pragma unroll
        for (int j = 0; j < 4; ++j) {
#pragma unroll
            for (int c = 0; c < 2; ++c) {
                int n = nb + j * 8 + c;
                float e = en[n];
                float s0 = fmaf(-2.0f, acc[j][c],     e);   // row l/4
                float s1 = fmaf(-2.0f, acc[j][2 + c], e);   // row l/4 + 8
                float t0 = fmaxf(m1a, s0);
                bool  p0 = s0 < m1a;
                m1a = fminf(m1a, s0);
                idxa = p0 ? n : idxa;
                m2a = fminf(m2a, t0);
                float t1 = fmaxf(m1b, s1);
                bool  p1 = s1 < m1b;
                m1b = fminf(m1b, s1);
                idxb = p1 ? n : idxb;
                m2b = fminf(m2b, t1);
            }
        }
    }

    // cross-lane reduce within 4-lane row group (xor 1, 2)
#pragma unroll
    for (int off = 1; off <= 2; off <<= 1) {
        float om1 = __shfl_xor_sync(0xffffffffu, m1a, off);
        float om2 = __shfl_xor_sync(0xffffffffu, m2a, off);
        int   oid = __shfl_xor_sync(0xffffffffu, idxa, off);
        m2a = fminf(fminf(m2a, om2), fmaxf(m1a, om1));
        bool p = (om1 < m1a) || (om1 == m1a && oid < idxa);
        m1a = p ? om1 : m1a; idxa = p ? oid : idxa;
        om1 = __shfl_xor_sync(0xffffffffu, m1b, off);
        om2 = __shfl_xor_sync(0xffffffffu, m2b, off);
        oid = __shfl_xor_sync(0xffffffffu, idxb, off);
        m2b = fminf(fminf(m2b, om2), fmaxf(m1b, om1));
        p = (om1 < m1b) || (om1 == m1b && oid < idxb);
        m1b = p ? om1 : m1b; idxb = p ? oid : idxb;
    }

    if ((lane & 3) == 0) {
        int row0 = rowBase + w * 16 + (lane >> 2);
        g_idx[row0]     = idxa;
        g_idx[row0 + 8] = idxb;
        if (m2a - m1a < MARGIN) { int p = atomicAdd(&g_nflag, 1); g_flagrows[p] = row0; }
        if (m2b - m1b < MARGIN) { int p = atomicAdd(&g_nflag, 1); g_flagrows[p] = row0 + 8; }
    }
}

// ---------------- exact fp32 fallback for narrow-margin rows ----------------
__global__ void vq_fallback(const float* __restrict__ x, const float* __restrict__ emb) {
    __shared__ float xr[64];
    __shared__ float rv[128];
    __shared__ int   ri[128];
    int nf = g_nflag;
    for (int f = (int)blockIdx.x; f < nf; f += gridDim.x) {
        int row = g_flagrows[f];
        __syncthreads();
        if (threadIdx.x < 64) xr[threadIdx.x] = x[row * 64 + threadIdx.x];
        __syncthreads();
        float bv = 3.0e38f; int bk = K_CODES;
        for (int k = threadIdx.x; k < K_CODES; k += 128) {
            float dot = 0.0f;
#pragma unroll
            for (int d = 0; d < 64; ++d) dot = fmaf(xr[d], emb[d * K_CODES + k], dot);
            float s = fmaf(-2.0f, dot, g_enorm[k]);
            if (s < bv) { bv = s; bk = k; }
        }
        rv[threadIdx.x] = bv; ri[threadIdx.x] = bk;
        __syncthreads();
        for (int st = 64; st > 0; st >>= 1) {
            if ((int)threadIdx.x < st) {
                float ov = rv[threadIdx.x + st]; int oi = ri[threadIdx.x + st];
                if (ov < rv[threadIdx.x] ||
                    (ov == rv[threadIdx.x] && oi < ri[threadIdx.x])) {
                    rv[threadIdx.x] = ov; ri[threadIdx.x] = oi;
                }
            }
            __syncthreads();
        }
        if (threadIdx.x == 0) g_idx[row] = ri[0];
    }
}

// ---------------- gather + loss ----------------
__global__ __launch_bounds__(256) void vq_gather(const float* __restrict__ x,
                                                 float* __restrict__ out) {
    __shared__ float red[512];
    float s1 = 0.0f, s2 = 0.0f;
    int base = blockIdx.x * 4096 + threadIdx.x;
#pragma unroll
    for (int j = 0; j < 16; ++j) {
        int i = base + j * 256;
        int row = i >> 6, d = i & 63;
        float q  = g_eT[g_idx[row] * 64 + d];
        float xv = x[i];
        out[i] = q;
        float dd = q - xv;
        s1 += dd;
        s2 += dd * dd;
    }
    red[threadIdx.x] = s1; red[256 + threadIdx.x] = s2;
    __syncthreads();
    for (int st = 128; st > 0; st >>= 1) {
        if ((int)threadIdx.x < st) {
            red[threadIdx.x]       += red[threadIdx.x + st];
            red[256 + threadIdx.x] += red[256 + threadIdx.x + st];
        }
        __syncthreads();
    }
    if (threadIdx.x == 0) { g_p1[blockIdx.x] = red[0]; g_p2[blockIdx.x] = red[256]; }
}

__global__ void vq_finalize(float* __restrict__ out, int out_size) {
    __shared__ float r1[GATHER_BLOCKS];
    __shared__ float r2[GATHER_BLOCKS];
    int t = threadIdx.x;
    r1[t] = g_p1[t]; r2[t] = g_p2[t];
    __syncthreads();
    for (int st = GATHER_BLOCKS / 2; st > 0; st >>= 1) {
        if (t < st) { r1[t] += r1[t + st]; r2[t] += r2[t + st]; }
        __syncthreads();
    }
    if (t == 0 && out_size > NTOT) {
        float inv = 1.0f / (float)NTOT;
        float m = r1[0] * inv;
        out[NTOT] = 0.25f * m * m + r2[0] * inv;
    }
}

// ---------------- host launch ----------------
extern "C" void kernel_launch(void* const* d_in, const int* in_sizes, int n_in,
                              void* d_out, int out_size) {
    const float* x   = (const float*)d_in[0];
    const float* emb = (const float*)d_in[1];
    if (n_in >= 2 && in_sizes[0] == K_CODES * D_DIM && in_sizes[1] == NTOT) {
        emb = (const float*)d_in[0];
        x   = (const float*)d_in[1];
    }
    float* out = (float*)d_out;

    cudaFuncSetAttribute(vq_gemm, cudaFuncAttributeMaxDynamicSharedMemorySize, SMEM_DYN);

    prep_e<<<K_CODES / 256, 256>>>(emb);
    vq_gemm<<<GEMM_CTAS, 256, SMEM_DYN>>>(x);
    vq_fallback<<<1024, 128>>>(x, emb);
    vq_gather<<<GATHER_BLOCKS, 256>>>(x, out);
    vq_finalize<<<1, GATHER_BLOCKS>>>(out, out_size);
}

// round 5
// speedup vs baseline: 3.9828x; 1.8540x over previous
#include <cuda_runtime.h>
#include <cuda_fp16.h>
#include <cstdint>

#define K_CODES 4096
#define D_DIM   64
#define N_ROWS  65536
#define NTOT    (N_ROWS * D_DIM)
#define NPC     32                   // codes per chunk
#define NCHUNK  (K_CODES / NPC)      // 128
#define GEMM_CTAS (N_ROWS / 128)     // 512
#define MARGIN  1.25e-3f
#define GATHER_BLOCKS 1024
#define FLT_BIG 3.0e38f

// ---------------- global scratch ----------------
__device__ float g_eT[K_CODES * D_DIM];     // codebook rows [k][d] fp32 (gather)
__device__ float g_enorm[K_CODES];          // ||e_k||^2 fp32
__device__ float g_enfrag[K_CODES];         // en reordered fragment-major (float2 pairs)
__device__ int   g_idx[N_ROWS];
__device__ int   g_nflag;
__device__ int   g_flagrows[N_ROWS];
__device__ float g_p1[GATHER_BLOCKS];
__device__ float g_p2[GATHER_BLOCKS];
// fp16 codebook in mma.sync B-fragment order: 16B per (chunk,kstep,qpair,lane)
__device__ __align__(16) uint4 g_Bfrag[NCHUNK * 4 * 2 * 32];    // 512 KB

// ---------------- asm helpers ----------------
#define MMA16816(d, a, b0, b1) \
    asm volatile("mma.sync.aligned.m16n8k16.row.col.f32.f16.f16.f32 " \
        "{%0,%1,%2,%3}, {%4,%5,%6,%7}, {%8,%9}, {%0,%1,%2,%3};" \
        : "+f"((d)[0]), "+f"((d)[1]), "+f"((d)[2]), "+f"((d)[3]) \
        : "r"((a)[0]), "r"((a)[1]), "r"((a)[2]), "r"((a)[3]), "r"(b0), "r"(b1))

static __device__ __forceinline__ uint32_t h2u(__half2 h) {
    union { __half2 h; uint32_t u; } c; c.h = h; return c.u;
}
static __device__ __forceinline__ uint32_t f2tohalf2(float a, float b) {
    return h2u(__floats2half2_rn(a, b));
}

// ---------------- prep 1: per-code norms, row-major copy, en fragment order ----------------
__global__ void prep_e(const float* __restrict__ emb) {
    int n = blockIdx.x * blockDim.x + threadIdx.x;
    if (n == 0) g_nflag = 0;
    if (n >= K_CODES) return;
    float acc = 0.0f;
#pragma unroll
    for (int d = 0; d < D_DIM; ++d) {
        float v = __ldg(&emb[d * K_CODES + n]);
        g_eT[n * D_DIM + d] = v;
        acc += v * v;
    }
    g_enorm[n] = acc;
    // fragment order: c=n>>5, r=n&31, j=r>>3, p=(r&7)>>1, e=r&1
    int c = n >> 5, r = n & 31;
    int j = r >> 3, p = (r & 7) >> 1, e = r & 1;
    g_enfrag[(((c * 4 + j) * 4) + p) * 2 + e] = acc;
}

// ---------------- prep 2: fp16 codebook in B-fragment order ----------------
// element idx = ((c*4 + s)*2 + q)*32 + lane ; 16B = [b0(j),b1(j),b0(j+1),b1(j+1)], j=2q
__global__ void prep_bfrag(const float* __restrict__ emb) {
    int id = blockIdx.x * blockDim.x + threadIdx.x;   // 0 .. 32767
    if (id >= NCHUNK * 4 * 2 * 32) return;
    int l = id & 31;
    int q = (id >> 5) & 1;
    int s = (id >> 6) & 3;
    int c = id >> 8;
    uint32_t w[4];
#pragma unroll
    for (int jj = 0; jj < 2; ++jj) {
        int n  = c * 32 + (2 * q + jj) * 8 + (l >> 2);
        int d0 = s * 16 + (l & 3) * 2;
        float b00 = __ldg(&emb[(d0    ) * K_CODES + n]);
        float b01 = __ldg(&emb[(d0 + 1) * K_CODES + n]);
        float b10 = __ldg(&emb[(d0 + 8) * K_CODES + n]);
        float b11 = __ldg(&emb[(d0 + 9) * K_CODES + n]);
        w[jj * 2]     = f2tohalf2(b00, b01);
        w[jj * 2 + 1] = f2tohalf2(b10, b11);
    }
    g_Bfrag[id] = make_uint4(w[0], w[1], w[2], w[3]);
}

// ---------------- main GEMM: no smem, no barriers ----------------
__global__ __launch_bounds__(256) void vq_gemm(const float* __restrict__ x) {
    const int tid  = threadIdx.x;
    const int lane = tid & 31;
    const int w    = tid >> 5;
    const int rowBase = blockIdx.x * 128 + w * 16;

    // A fragments direct from gmem (fp32 -> fp16), held all loop
    uint32_t afr[4][4];
    {
        const int rA = rowBase + (lane >> 2);
        const int kc = (lane & 3) * 2;
#pragma unroll
        for (int s = 0; s < 4; ++s) {
            const float* p0 = x + (size_t)rA * 64 + s * 16 + kc;
            const float* p1 = p0 + 8 * 64;           // row +8
            float2 a0 = __ldg((const float2*)p0);
            float2 a1 = __ldg((const float2*)p1);
            float2 a2 = __ldg((const float2*)(p0 + 8));
            float2 a3 = __ldg((const float2*)(p1 + 8));
            afr[s][0] = f2tohalf2(a0.x, a0.y);
            afr[s][1] = f2tohalf2(a1.x, a1.y);
            afr[s][2] = f2tohalf2(a2.x, a2.y);
            afr[s][3] = f2tohalf2(a3.x, a3.y);
        }
    }

    float m1a = FLT_BIG, m2a = FLT_BIG, m1b = FLT_BIG, m2b = FLT_BIG;
    int idxa = 0, idxb = 0;

    const uint4* bp = g_Bfrag + lane;
    const float2* enf = (const float2*)g_enfrag + (lane & 3);

    for (int c = 0; c < NCHUNK; ++c) {
        float acc[4][4];
#pragma unroll
        for (int j = 0; j < 4; ++j)
#pragma unroll
            for (int i = 0; i < 4; ++i) acc[j][i] = 0.0f;

#pragma unroll
        for (int s = 0; s < 4; ++s) {
            uint4 B0 = __ldg(bp);
            uint4 B1 = __ldg(bp + 32);
            bp += 64;
            MMA16816(acc[0], afr[s], B0.x, B0.y);
            MMA16816(acc[1], afr[s], B0.z, B0.w);
            MMA16816(acc[2], afr[s], B1.x, B1.y);
            MMA16816(acc[3], afr[s], B1.z, B1.w);
        }

        // scores
        float s0[8], s1[8];
#pragma unroll
        for (int j = 0; j < 4; ++j) {
            float2 en = __ldg(enf + (size_t)(c * 4 + j) * 4);
            s0[2 * j]     = fmaf(-2.0f, acc[j][0], en.x);
            s0[2 * j + 1] = fmaf(-2.0f, acc[j][1], en.y);
            s1[2 * j]     = fmaf(-2.0f, acc[j][2], en.x);
            s1[2 * j + 1] = fmaf(-2.0f, acc[j][3], en.y);
        }
        // index-free chunk minima (trees)
        float cA = fminf(fminf(fminf(s0[0], s0[1]), fminf(s0[2], s0[3])),
                         fminf(fminf(s0[4], s0[5]), fminf(s0[6], s0[7])));
        float cB = fminf(fminf(fminf(s1[0], s1[1]), fminf(s1[2], s1[3])),
                         fminf(fminf(s1[4], s1[5]), fminf(s1[6], s1[7])));

        if (cA < m1a || cB < m1b) {          // rare: resolve index + second
            const int nb = c * 32 + (lane & 3) * 2;
            if (cA < m1a) {
                float v1 = FLT_BIG, v2 = FLT_BIG; int id = 0;
#pragma unroll
                for (int i = 0; i < 8; ++i) {
                    int n = nb + (i >> 1) * 8 + (i & 1);
                    float t = fmaxf(v1, s0[i]);
                    bool  p = s0[i] < v1;
                    v1 = fminf(v1, s0[i]);
                    v2 = fminf(v2, t);
                    id = p ? n : id;
                }
                m2a = fminf(m1a, v2); m1a = v1; idxa = id;
            } else {
                m2a = fminf(m2a, cA);
            }
            if (cB < m1b) {
                float v1 = FLT_BIG, v2 = FLT_BIG; int id = 0;
#pragma unroll
                for (int i = 0; i < 8; ++i) {
                    int n = nb + (i >> 1) * 8 + (i & 1);
                    float t = fmaxf(v1, s1[i]);
                    bool  p = s1[i] < v1;
                    v1 = fminf(v1, s1[i]);
                    v2 = fminf(v2, t);
                    id = p ? n : id;
                }
                m2b = fminf(m1b, v2); m1b = v1; idxb = id;
            } else {
                m2b = fminf(m2b, cB);
            }
        } else {
            m2a = fminf(m2a, cA);
            m2b = fminf(m2b, cB);
        }
    }

    // cross-lane merge within 4-lane row group
#pragma unroll
    for (int off = 1; off <= 2; off <<= 1) {
        float om1 = __shfl_xor_sync(0xffffffffu, m1a, off);
        float om2 = __shfl_xor_sync(0xffffffffu, m2a, off);
        int   oid = __shfl_xor_sync(0xffffffffu, idxa, off);
        m2a = fminf(fminf(m2a, om2), fmaxf(m1a, om1));
        bool p = (om1 < m1a) || (om1 == m1a && oid < idxa);
        m1a = p ? om1 : m1a; idxa = p ? oid : idxa;
        om1 = __shfl_xor_sync(0xffffffffu, m1b, off);
        om2 = __shfl_xor_sync(0xffffffffu, m2b, off);
        oid = __shfl_xor_sync(0xffffffffu, idxb, off);
        m2b = fminf(fminf(m2b, om2), fmaxf(m1b, om1));
        p = (om1 < m1b) || (om1 == m1b && oid < idxb);
        m1b = p ? om1 : m1b; idxb = p ? oid : idxb;
    }

    if ((lane & 3) == 0) {
        int row0 = rowBase + (lane >> 2);
        g_idx[row0]     = idxa;
        g_idx[row0 + 8] = idxb;
        if (m2a - m1a < MARGIN) { int p = atomicAdd(&g_nflag, 1); g_flagrows[p] = row0; }
        if (m2b - m1b < MARGIN) { int p = atomicAdd(&g_nflag, 1); g_flagrows[p] = row0 + 8; }
    }
}

// ---------------- exact fp32 fallback for narrow-margin rows ----------------
__global__ void vq_fallback(const float* __restrict__ x, const float* __restrict__ emb) {
    __shared__ float xr[64];
    __shared__ float rv[128];
    __shared__ int   ri[128];
    int nf = g_nflag;
    for (int f = (int)blockIdx.x; f < nf; f += gridDim.x) {
        int row = g_flagrows[f];
        __syncthreads();
        if (threadIdx.x < 64) xr[threadIdx.x] = x[row * 64 + threadIdx.x];
        __syncthreads();
        float bv = FLT_BIG; int bk = K_CODES;
        for (int k = threadIdx.x; k < K_CODES; k += 128) {
            float dot = 0.0f;
#pragma unroll
            for (int d = 0; d < 64; ++d) dot = fmaf(xr[d], emb[d * K_CODES + k], dot);
            float s = fmaf(-2.0f, dot, g_enorm[k]);
            if (s < bv) { bv = s; bk = k; }
        }
        rv[threadIdx.x] = bv; ri[threadIdx.x] = bk;
        __syncthreads();
        for (int st = 64; st > 0; st >>= 1) {
            if ((int)threadIdx.x < st) {
                float ov = rv[threadIdx.x + st]; int oi = ri[threadIdx.x + st];
                if (ov < rv[threadIdx.x] ||
                    (ov == rv[threadIdx.x] && oi < ri[threadIdx.x])) {
                    rv[threadIdx.x] = ov; ri[threadIdx.x] = oi;
                }
            }
            __syncthreads();
        }
        if (threadIdx.x == 0) g_idx[row] = ri[0];
    }
}

// ---------------- gather + loss ----------------
__global__ __launch_bounds__(256) void vq_gather(const float* __restrict__ x,
                                                 float* __restrict__ out) {
    __shared__ float red[512];
    float s1 = 0.0f, s2 = 0.0f;
    int base = blockIdx.x * 4096 + threadIdx.x;
#pragma unroll
    for (int j = 0; j < 16; ++j) {
        int i = base + j * 256;
        int row = i >> 6, d = i & 63;
        float q  = g_eT[g_idx[row] * 64 + d];
        float xv = x[i];
        out[i] = q;
        float dd = q - xv;
        s1 += dd;
        s2 += dd * dd;
    }
    red[threadIdx.x] = s1; red[256 + threadIdx.x] = s2;
    __syncthreads();
    for (int st = 128; st > 0; st >>= 1) {
        if ((int)threadIdx.x < st) {
            red[threadIdx.x]       += red[threadIdx.x + st];
            red[256 + threadIdx.x] += red[256 + threadIdx.x + st];
        }
        __syncthreads();
    }
    if (threadIdx.x == 0) { g_p1[blockIdx.x] = red[0]; g_p2[blockIdx.x] = red[256]; }
}

__global__ void vq_finalize(float* __restrict__ out, int out_size) {
    __shared__ float r1[GATHER_BLOCKS];
    __shared__ float r2[GATHER_BLOCKS];
    int t = threadIdx.x;
    r1[t] = g_p1[t]; r2[t] = g_p2[t];
    __syncthreads();
    for (int st = GATHER_BLOCKS / 2; st > 0; st >>= 1) {
        if (t < st) { r1[t] += r1[t + st]; r2[t] += r2[t + st]; }
        __syncthreads();
    }
    if (t == 0 && out_size > NTOT) {
        float inv = 1.0f / (float)NTOT;
        float m = r1[0] * inv;
        out[NTOT] = 0.25f * m * m + r2[0] * inv;
    }
}

// ---------------- host launch ----------------
extern "C" void kernel_launch(void* const* d_in, const int* in_sizes, int n_in,
                              void* d_out, int out_size) {
    const float* x   = (const float*)d_in[0];
    const float* emb = (const float*)d_in[1];
    if (n_in >= 2 && in_sizes[0] == K_CODES * D_DIM && in_sizes[1] == NTOT) {
        emb = (const float*)d_in[0];
        x   = (const float*)d_in[1];
    }
    float* out = (float*)d_out;

    prep_e<<<K_CODES / 256, 256>>>(emb);
    prep_bfrag<<<(NCHUNK * 4 * 2 * 32) / 256, 256>>>(emb);
    vq_gemm<<<GEMM_CTAS, 256>>>(x);
    vq_fallback<<<1024, 128>>>(x, emb);
    vq_gather<<<GATHER_BLOCKS, 256>>>(x, out);
    vq_finalize<<<1, GATHER_BLOCKS>>>(out, out_size);
}